// round 14
// baseline (speedup 1.0000x reference)
#include <cuda_runtime.h>
#include <cstdint>
#include <math.h>

#define N_RAYS    65536
#define N_SAMPLES 192
#define NPAIRG    3                     // 3 groups of 64 samples (2 per lane)
#define EPSV      1e-10f
#define WARPS_PER_BLOCK 4
#define THREADS   (WARPS_PER_BLOCK * 32)

// Output layout: flattened tuple concat
#define OFF_RGB   0
#define OFF_DENS  (N_RAYS * 3)
#define OFF_ACC   (N_RAYS * 194)
#define OFF_W     (N_RAYS * 195)
#define OFF_DEPTH (N_RAYS * 387)

__device__ __forceinline__ float fast_sigmoid(float x) {
    float t;
    asm("tanh.approx.f32 %0, %1;" : "=f"(t) : "f"(x * 0.5f));
    return fmaf(t, 0.5f, 0.5f);
}

__device__ __forceinline__ void cp_async16(unsigned int smem_addr, const void* gptr) {
    asm volatile("cp.async.cg.shared.global [%0], [%1], 16;"
                 :: "r"(smem_addr), "l"(gptr));
}
__device__ __forceinline__ void cp_commit() {
    asm volatile("cp.async.commit_group;");
}
template <int N>
__device__ __forceinline__ void cp_wait() {
    asm volatile("cp.async.wait_group %0;" :: "n"(N));
}

__global__ __launch_bounds__(THREADS, 14)
void nerf_volrender_kernel(const float4* __restrict__ raw4,
                           const float*  __restrict__ z_vals,
                           const float*  __restrict__ rays_d,
                           float*        __restrict__ out)
{
    const unsigned FULL = 0xFFFFFFFFu;
    const int wib   = threadIdx.x >> 5;
    const int lane  = threadIdx.x & 31;
    const int r     = blockIdx.x * WARPS_PER_BLOCK + wib;   // one warp per ray

    __shared__ float4 sraw[WARPS_PER_BLOCK][N_SAMPLES];     // 12 KB, warp-private

    const int zbase = r * N_SAMPLES;

    // ---- issue 6 raw copies as 3 commit groups (one per 64-sample group) ----
    unsigned int sbase = (unsigned int)__cvta_generic_to_shared(&sraw[wib][0]);
    #pragma unroll
    for (int g = 0; g < NPAIRG; g++) {
        int s0 = g * 64 + 2 * lane;                         // lane's 32 B
        cp_async16(sbase + (unsigned int)s0 * 16u,       &raw4[zbase + s0]);
        cp_async16(sbase + (unsigned int)(s0 + 1) * 16u, &raw4[zbase + s0 + 1]);
        cp_commit();
    }

    // ---- z loads: float2 per lane per group (coalesced LDG.64) ----
    float2 zf[NPAIRG];
    #pragma unroll
    for (int g = 0; g < NPAIRG; g++)
        zf[g] = __ldcs((const float2*)&z_vals[zbase + g * 64] + lane);

    float dx = __ldg(&rays_d[r * 3 + 0]);
    float dy = __ldg(&rays_d[r * 3 + 1]);
    float dz = __ldg(&rays_d[r * 3 + 2]);
    float dnorm = sqrtf(dx * dx + dy * dy + dz * dz);

    float off = 1.0f;
    float sr = 0.f, sg = 0.f, sb = 0.f, sw = 0.f, sd = 0.f;

    #pragma unroll
    for (int g = 0; g < NPAIRG; g++) {
        if (g == 0)      { cp_wait<2>(); __syncwarp(); }
        else if (g == 1) { cp_wait<1>(); __syncwarp(); }
        else             { cp_wait<0>(); __syncwarp(); }

        const int s0 = g * 64 + 2 * lane;
        const float z0 = zf[g].x;
        const float z1 = zf[g].y;

        // z[s0+2]: next lane's z0; lane 31 takes next group's lane-0 z0
        float z2 = __shfl_down_sync(FULL, z0, 1);
        if (g < NPAIRG - 1) {
            float znext0 = __shfl_sync(FULL, zf[g + 1].x, 0);
            if (lane == 31) z2 = znext0;
        }
        float dist0 = fabsf(z1 - z0) * dnorm;
        float dist1 = fabsf(z2 - z1) * dnorm;

        const float4 rv0 = sraw[wib][s0];
        const float4 rv1 = sraw[wib][s0 + 1];

        float dens0 = fmaxf(rv0.w, 0.0f);
        float dens1 = fmaxf(rv1.w, 0.0f);
        // density: s0 always < 191; s1 = s0+1 < 191 except the global last
        __stcs(&out[OFF_DENS + r * (N_SAMPLES - 1) + s0], dens0);
        if (s0 + 1 < N_SAMPLES - 1)
            __stcs(&out[OFF_DENS + r * (N_SAMPLES - 1) + s0 + 1], dens1);

        bool last1 = (s0 + 1 == N_SAMPLES - 1);
        float alpha0 = 1.0f - __expf(-dens0 * dist0);
        float alpha1 = last1 ? 1.0f : (1.0f - __expf(-dens1 * dist1));
        float t0 = (1.0f + EPSV) - alpha0;
        float t1 = (1.0f + EPSV) - alpha1;

        // scan of PAIR products (one 5-step scan per 64 samples)
        float pair = t0 * t1;
        float P = pair;
        #pragma unroll
        for (int d = 1; d < 32; d <<= 1) {
            float o = __shfl_up_sync(FULL, P, d);
            if (lane >= d) P *= o;
        }

        float exclP = __shfl_up_sync(FULL, P, 1);
        if (lane == 0) exclP = 1.0f;
        float trans0 = off * exclP;          // exclusive cumprod at s0
        float trans1 = trans0 * t0;          // exclusive cumprod at s0+1
        // w = alpha*trans = ((1+eps) - t)*trans, computed exactly
        float w0 = fmaf(EPSV, trans0, fmaf(-t0, trans0, trans0));
        float w1 = fmaf(EPSV, trans1, fmaf(-t1, trans1, trans1));

        // weights: contiguous pair -> one STG.64 ((r*192 + s0) is even)
        float2 wpair = make_float2(w0, w1);
        __stcs((float2*)&out[OFF_W + r * N_SAMPLES + s0], wpair);

        sr += w0 * fast_sigmoid(rv0.x) + w1 * fast_sigmoid(rv1.x);
        sg += w0 * fast_sigmoid(rv0.y) + w1 * fast_sigmoid(rv1.y);
        sb += w0 * fast_sigmoid(rv0.z) + w1 * fast_sigmoid(rv1.z);
        sw += w0 + w1;
        sd += w0 * z0 + w1 * z1;

        off *= __shfl_sync(FULL, P, 31);
    }

    // warp reduction of the 5 accumulators
    #pragma unroll
    for (int d = 16; d > 0; d >>= 1) {
        sr += __shfl_down_sync(FULL, sr, d);
        sg += __shfl_down_sync(FULL, sg, d);
        sb += __shfl_down_sync(FULL, sb, d);
        sw += __shfl_down_sync(FULL, sw, d);
        sd += __shfl_down_sync(FULL, sd, d);
    }
    if (lane == 0) {
        out[OFF_RGB + r * 3 + 0] = sr;
        out[OFF_RGB + r * 3 + 1] = sg;
        out[OFF_RGB + r * 3 + 2] = sb;
        out[OFF_ACC   + r] = sw;
        out[OFF_DEPTH + r] = sd;
    }
}

extern "C" void kernel_launch(void* const* d_in, const int* in_sizes, int n_in,
                              void* d_out, int out_size)
{
    const float4* raw4   = (const float4*)d_in[0];
    const float*  z_vals = (const float*)d_in[1];
    const float*  rays_d = (const float*)d_in[2];
    float* out = (float*)d_out;

    const int blocks = N_RAYS / WARPS_PER_BLOCK;   // 16384
    nerf_volrender_kernel<<<blocks, THREADS>>>(raw4, z_vals, rays_d, out);
}